// round 17
// baseline (speedup 1.0000x reference)
#include <cuda_runtime.h>
#include <math.h>

#define NPASS 16
#define NFACE 640
#define NVERT 642
#define IMH 160
#define IMW 160
#define HW (IMH*IMW)
#define STEP (2.0f/159.0f)
#define NCHUNK 2
#define NPCH 160          // max face-pairs per chunk (ceil(640/2)/2)

// gaussian 11-tap weights (fp64 exp/normalize, rounded to float)
#define G0 1.4867195e-06f
#define G1 1.3383023e-04f
#define G2 4.4318484e-03f
#define G3 5.3990966e-02f
#define G4 2.4197073e-01f
#define G5 3.9894228e-01f
__device__ __constant__ float c_gauss[11]={G0,G1,G2,G3,G4,G5,G4,G3,G2,G1,G0};

typedef unsigned long long ull;

// packed f32x2 helpers (fma only — min/max.f32x2 do NOT exist on sm_103a)
#define FMA2(d,a,b,c) asm("fma.rn.f32x2 %0, %1, %2, %3;" : "=l"(d) : "l"(a), "l"(b), "l"(c))
#define PK2(d,x) { unsigned _u=__float_as_uint(x); asm("mov.b64 %0, {%1,%2};" : "=l"(d) : "r"(_u), "r"(_u)); }
#define UPK(lo,hi,v) { unsigned _a,_b; asm("mov.b64 {%0,%1}, %2;" : "=r"(_a), "=r"(_b) : "l"(v)); lo=__uint_as_float(_a); hi=__uint_as_float(_b); }

// ---------------- scratch ----------------
__device__ float  g_rec[NPASS*NFACE*12];    // compacted face records: {A0,B0,C0,Za, A1,B1,C1,Zb, A2,B2,C2,Zc}
__device__ int    g_sid[NPASS*NFACE];       // original face id per compact slot
__device__ int    g_nvalid[NPASS];
__device__ float  g_pmm[NCHUNK*NPASS*HW];   // per-chunk partials
__device__ float  g_pz [NCHUNK*NPASS*HW];
__device__ int    g_pidx[NCHUNK*NPASS*HW];
__device__ float  g_feats[NPASS*3*HW];
__device__ float  g_soft[NPASS*HW];

// ---------------- helpers ----------------
__device__ void quat_rod(const float* q, float scale, float* R){
    float w=q[0], x=q[1], y=q[2], z=q[3];
    float sn=sqrtf(x*x+y*y+z*z);
    float tt = 2.0f*((w<0.0f)? atan2f(-sn,-w) : atan2f(sn,w));
    float k = (sn>1e-8f)? (tt/fmaxf(sn,1e-8f)) : 2.0f;
    k *= scale;
    float ax=x*k, ay=y*k, az=z*k;
    float th=sqrtf(ax*ax+ay*ay+az*az);
    float inv=1.0f/fmaxf(th,1e-8f);
    float ux=ax*inv, uy=ay*inv, uz=az*inv;
    float s=sinf(th), c=cosf(th), cc=1.0f-c;
    R[0]=1.0f+cc*(-(uy*uy+uz*uz)); R[1]=-s*uz+cc*(ux*uy);          R[2]= s*uy+cc*(ux*uz);
    R[3]= s*uz+cc*(ux*uy);         R[4]=1.0f+cc*(-(ux*ux+uz*uz));  R[5]=-s*ux+cc*(uy*uz);
    R[6]=-s*uy+cc*(ux*uz);         R[7]= s*ux+cc*(uy*uz);          R[8]=1.0f+cc*(-(ux*ux+uy*uy));
}

__device__ void compute_RT(int p, const float* quat, const float* trans,
                           float* sR, float* sT){
    int f=p>>3, st=p&7;
    float R[9], Rs[9];
    quat_rod(&quat[(f*2+1)*4], 1.0f, R);
    quat_rod(&quat[(f*2+0)*4], 1.0f/16.0f, Rs);
    for(int s=0;s<st;s++){
        float Rn[9];
        for(int a=0;a<3;a++)
            for(int b=0;b<3;b++)
                Rn[a*3+b]=R[a*3+0]*Rs[0*3+b]+R[a*3+1]*Rs[1*3+b]+R[a*3+2]*Rs[2*3+b];
        for(int k=0;k<9;k++) R[k]=Rn[k];
    }
    for(int k=0;k<9;k++) sR[k]=R[k];
    float ti=(float)st*(1.0f/7.0f);
    for(int k=0;k<3;k++)
        sT[k]=trans[(f*2+1)*3+k] + ti*trans[(f*2+0)*3+k] - ((k==2)?2.0f:0.0f);
}

__device__ __forceinline__ void xform(const float* uv, const float* R, const float* T,
                                      int n, float& vx, float& vy, float& vz){
    float ux=uv[n*3+0], uy=uv[n*3+1], uz=uv[n*3+2];
    vx=R[0]*ux+R[1]*uy+R[2]*uz + T[0];
    vy=R[3]*ux+R[4]*uy+R[5]*uz + T[1];
    vz=R[6]*ux+R[7]*uy+R[8]*uz + T[2];
}

__device__ __forceinline__ bool face_record_g(const float* uv, const float* R, const float* T,
                                              const int* faces, int i,
                                              float4& r0, float4& r1, float4& r2){
    int i0=faces[i*3+0], i1=faces[i*3+1], i2=faces[i*3+2];
    float ax3,ay3,az3, bx3,by3,bz3, cx3,cy3,cz3;
    xform(uv,R,T,i0,ax3,ay3,az3);
    xform(uv,R,T,i1,bx3,by3,bz3);
    xform(uv,R,T,i2,cx3,cy3,cz3);
    float nz=(bx3-ax3)*(cy3-ay3)-(by3-ay3)*(cx3-ax3);
    const float F=(float)(1.0/tan(1.57/4.0));   // exact reference focal (NOT pi/8)
    float ax=(ax3*F)/(-az3), ay=(ay3*F)/(-az3);
    float bx=(bx3*F)/(-bz3), by=(by3*F)/(-bz3);
    float cx=(cx3*F)/(-cz3), cy=(cy3*F)/(-cz3);
    float denom=(bx-ax)*(cy-ay)-(by-ay)*(cx-ax);
    bool valid=(nz>0.0f)&&(fabsf(denom)>1e-9f);
    if(valid){
        float inv=1.0f/denom;
        float A0=(bx*cy-by*cx)*inv, B0=(by-cy)*inv, C0=(cx-bx)*inv;
        float A1=(cx*ay-cy*ax)*inv, B1=(cy-ay)*inv, C1=(ax-cx)*inv;
        float A2=(ax*by-ay*bx)*inv, B2=(ay-by)*inv, C2=(bx-ax)*inv;
        float Za=A0*az3+A1*bz3+A2*cz3;
        float Zb=B0*az3+B1*bz3+B2*cz3;
        float Zc=C0*az3+C1*bz3+C2*cz3;
        r0=make_float4(A0,B0,C0,Za);
        r1=make_float4(A1,B1,C1,Zb);
        r2=make_float4(A2,B2,C2,Zc);
    }
    return valid;
}

// store face record into pair-interleaved SoA (stride NPCH pairs):
// coeff order [A0,B0, C0,A1, B1,C1, A2,B2, C2,Za, Zb,Zc]
__device__ __forceinline__ void store_face_ch(float* fv, int pos,
                                              float4 r0, float4 r1, float4 r2){
    int h=pos>>1, o=pos&1, b=h*4+o;
    fv[0*4*NPCH+b]=r0.x;  fv[0*4*NPCH+b+2]=r0.y;
    fv[1*4*NPCH+b]=r0.z;  fv[1*4*NPCH+b+2]=r1.x;
    fv[2*4*NPCH+b]=r1.y;  fv[2*4*NPCH+b+2]=r1.z;
    fv[3*4*NPCH+b]=r2.x;  fv[3*4*NPCH+b+2]=r2.y;
    fv[4*4*NPCH+b]=r2.z;  fv[4*4*NPCH+b+2]=r0.w;
    fv[5*4*NPCH+b]=r1.w;  fv[5*4*NPCH+b+2]=r2.w;
}

// ---------------- kernel 1: geometry (compacted records to global) ----------------
__global__ void __launch_bounds__(640) k_geom(const float* __restrict__ uv,
                                              const int* __restrict__ faces,
                                              const float* __restrict__ quat,
                                              const float* __restrict__ trans){
    int p=blockIdx.x; int i=threadIdx.x;
    __shared__ float sR[9], sT[3];
    __shared__ int wcnt[20], wbase[20];
    if(i==0) compute_RT(p, quat, trans, sR, sT);
    __syncthreads();
    int lane=i&31, wid=i>>5;
    float4 r0,r1,r2;
    bool valid=face_record_g(uv, sR, sT, faces, i, r0, r1, r2);
    unsigned bal=__ballot_sync(0xffffffffu, valid);
    if(lane==0) wcnt[wid]=__popc(bal);
    __syncthreads();
    if(i==0){
        int acc=0;
        for(int w=0;w<20;w++){ wbase[w]=acc; acc+=wcnt[w]; }
        g_nvalid[p]=acc;
    }
    __syncthreads();
    if(valid){
        int pos=wbase[wid]+__popc(bal&((1u<<lane)-1u));
        float4* rec=(float4*)&g_rec[(p*NFACE+pos)*12];
        rec[0]=r0; rec[1]=r1; rec[2]=r2;
        g_sid[p*NFACE+pos]=i;
    }
}

// ---------------- kernel 2: chunked raster -> partials ----------------
// grid (NCHUNK, 40, NPASS), block 128: warp w = row band*4+w, chunk c faces
__global__ void __launch_bounds__(128,7) k_raster(){
    __shared__ __align__(16) float fv[6*4*NPCH];
    int c=blockIdx.x, band=blockIdx.y, p=blockIdx.z;
    int tid=threadIdx.x;
    int lane=tid&31, wid=tid>>5;

    int m=g_nvalid[p];
    int half=(m+1)>>1;
    int start=c*half;
    int end=min(m, start+half);
    int cn=end-start; if(cn<0) cn=0;

    for(int i=tid; i<cn; i+=128){
        const float4* rec=(const float4*)&g_rec[(p*NFACE+start+i)*12];
        store_face_ch(fv, i, rec[0], rec[1], rec[2]);
    }
    if(tid==0 && (cn&1)){
        float4 s=make_float4(-1e9f,0.f,0.f,0.f);
        store_face_ch(fv, cn, s, s, s);
    }
    __syncthreads();

    int y=band*4+wid;
    float pyv = 1.0f - (float)y*STEP;
    float px0 = fmaf((float)lane, STEP, -1.0f);
    float pxs[5];
    #pragma unroll
    for(int i=0;i<5;i++) pxs[i]=px0+(32.0f*STEP)*(float)i;
    ull px2[5], pyv2;
    #pragma unroll
    for(int i=0;i<5;i++) PK2(px2[i], pxs[i]);
    PK2(pyv2, pyv);

    float mm[5], bzv[5]; int biv[5];
    #pragma unroll
    for(int i=0;i<5;i++){ mm[i]=-3.0e38f; bzv[i]=-1e9f; biv[i]=-1; }

    int mp=(cn+1)>>1;
    const ulonglong2* V0=(const ulonglong2*)(fv+0*4*NPCH);
    const ulonglong2* V1=(const ulonglong2*)(fv+1*4*NPCH);
    const ulonglong2* V2=(const ulonglong2*)(fv+2*4*NPCH);
    const ulonglong2* V3=(const ulonglong2*)(fv+3*4*NPCH);
    const ulonglong2* V4=(const ulonglong2*)(fv+4*4*NPCH);
    const ulonglong2* V5=(const ulonglong2*)(fv+5*4*NPCH);

    for(int h=0; h<mp; h++){
        ulonglong2 q0=V0[h], q1=V1[h], q2=V2[h], q3=V3[h], q4=V4[h], q5=V5[h];
        ull w0b,w1b,w2b,zbp;
        FMA2(w0b, q1.x, pyv2, q0.x);
        FMA2(w1b, q2.y, pyv2, q1.y);
        FMA2(w2b, q4.x, pyv2, q3.x);
        FMA2(zbp, q5.y, pyv2, q4.y);
        #pragma unroll
        for(int i=0;i<5;i++){
            ull w0,w1,w2,zz;
            FMA2(w0, q0.y, px2[i], w0b);
            FMA2(w1, q2.x, px2[i], w1b);
            FMA2(w2, q3.y, px2[i], w2b);
            FMA2(zz, q5.x, px2[i], zbp);
            float w0f,w0g,w1f,w1g,w2f,w2g,zf,zg;
            UPK(w0f,w0g,w0); UPK(w1f,w1g,w1); UPK(w2f,w2g,w2); UPK(zf,zg,zz);
            float mnf=fminf(w0f,fminf(w1f,w2f));
            float mng=fminf(w0g,fminf(w1g,w2g));
            mm[i]=fmaxf(mm[i],fmaxf(mnf,mng));
            if(mnf>=-1e-6f && zf>bzv[i]){ bzv[i]=zf; biv[i]=2*h; }
            if(mng>=-1e-6f && zg>bzv[i]){ bzv[i]=zg; biv[i]=2*h+1; }
        }
    }

    int base=(c*NPASS+p)*HW + y*IMW;
    #pragma unroll
    for(int i=0;i<5;i++){
        int x=lane+32*i;
        g_pmm[base+x]=mm[i];
        g_pz [base+x]=bzv[i];
        g_pidx[base+x]= (biv[i]>=0)? (start+biv[i]) : -1;
    }
}

// ---------------- kernel 3: merge partials -> soft + feats ----------------
__global__ void __launch_bounds__(256) k_merge(const float* __restrict__ ffeat){
    int idx=blockIdx.x*256+threadIdx.x;
    if(idx>=NPASS*HW) return;
    int p=idx/HW, rem=idx%HW, y=rem/IMW, x=rem%IMW;

    float mm=-3.0e38f, bz=-1e9f; int bi=-1;
    #pragma unroll
    for(int c=0;c<NCHUNK;c++){
        int o=(c*NPASS+p)*HW+rem;
        mm=fmaxf(mm, g_pmm[o]);
        float cz=g_pz[o]; int ci=g_pidx[o];
        if(ci>=0 && cz>bz){ bz=cz; bi=ci; }
    }

    float soft=1.0f/(1.0f+expf(-7000.0f*mm));
    g_soft[p*HW+rem]=soft;

    float f0=0.f,f1=0.f,f2=0.f;
    if(bi>=0){
        const float* rec=&g_rec[(p*NFACE+bi)*12];
        float pxv=fmaf((float)x, STEP, -1.0f);
        float pyv=1.0f-(float)y*STEP;
        float w0=fmaf(rec[1],pxv,fmaf(rec[2],pyv,rec[0]));
        float w1=fmaf(rec[5],pxv,fmaf(rec[6],pyv,rec[4]));
        float w2=fmaf(rec[9],pxv,fmaf(rec[10],pyv,rec[8]));
        const float* ff=&ffeat[g_sid[p*NFACE+bi]*9];
        f0=w0*ff[0]+w1*ff[3]+w2*ff[6];
        f1=w0*ff[1]+w1*ff[4]+w2*ff[7];
        f2=w0*ff[2]+w1*ff[5]+w2*ff[8];
    }
    int bo=p*3*HW+rem;
    g_feats[bo      ]=f0;
    g_feats[bo+  HW ]=f1;
    g_feats[bo+2*HW ]=f2;
}

// ---------------- kernel 4: post (8-row tiles, rgb blur or mask chain) ----------------
__device__ void post_task8(float* bufA, float* bufB, int t,
                           float* __restrict__ out, int tid, int nt){
    if(t<960){
        int img=t/20, tile=t%20, y0=tile*8;
        const float* in=&g_feats[img*HW];
        for(int idx=tid; idx<18*160; idx+=nt){
            int r=idx/160, x=idx%160;
            int yy=y0-5+r;
            yy = yy<0 ? -yy : (yy>IMH-1 ? 2*(IMH-1)-yy : yy);
            bufA[idx]=in[yy*IMW+x];
        }
        __syncthreads();
        for(int idx=tid; idx<8*160; idx+=nt){
            int j=idx/160, x=idx%160;
            float acc=0.f;
            #pragma unroll
            for(int k=0;k<11;k++) acc += c_gauss[k]*bufA[(j+k)*160+x];
            bufB[idx]=acc;
        }
        __syncthreads();
        int p=img/3, c=img%3;
        float* o=&out[(p*4+c)*HW];
        for(int idx=tid; idx<8*160; idx+=nt){
            int j=idx/160, x=idx%160;
            float acc=0.f;
            #pragma unroll
            for(int k=0;k<11;k++){
                int xx=x+k-5;
                xx = xx<0 ? -xx : (xx>IMW-1 ? 2*(IMW-1)-xx : xx);
                acc += c_gauss[k]*bufB[j*160+xx];
            }
            o[(y0+j)*IMW+x]=acc;
        }
    } else {
        int mt=t-960;
        int p=mt/20, tile=mt%20, y0=tile*8;
        const float* in=&g_soft[p*HW];
        for(int idx=tid; idx<30*160; idx+=nt){
            int r=idx/160, x=idx%160;
            int yy=y0-11+r;
            if(yy>=0 && yy<IMH) bufA[idx]=in[yy*IMW+x];
        }
        __syncthreads();
        for(int idx=tid; idx<28*160; idx+=nt){
            int r=idx/160, x=idx%160;
            int yy=y0-10+r;
            if(yy<0 || yy>=IMH) continue;
            float mval=3.4e38f;
            #pragma unroll
            for(int dy=-1;dy<=1;dy++){
                int ry=yy+dy; if(ry<0||ry>=IMH) continue;
                int sr=ry-(y0-11);
                #pragma unroll
                for(int dx=-1;dx<=1;dx++){
                    int xx=x+dx; if(xx<0||xx>=IMW) continue;
                    mval=fminf(mval, bufA[sr*160+xx]);
                }
            }
            bufB[idx]=mval;
        }
        __syncthreads();
        for(int idx=tid; idx<18*160; idx+=nt){
            int r=idx/160, x=idx%160;
            int yb=y0-5+r;
            if(yb<0 || yb>=IMH) continue;
            float acc=0.f;
            #pragma unroll
            for(int k=0;k<11;k++){
                int yy=yb+k-5;
                yy = yy<0 ? -yy : (yy>IMH-1 ? 2*(IMH-1)-yy : yy);
                acc += c_gauss[k]*bufB[(yy-(y0-10))*160+x];
            }
            bufA[idx]=acc;
        }
        __syncthreads();
        for(int idx=tid; idx<18*160; idx+=nt){
            int r=idx/160, x=idx%160;
            int yb=y0-5+r;
            if(yb<0 || yb>=IMH) continue;
            float acc=0.f;
            #pragma unroll
            for(int k=0;k<11;k++){
                int xx=x+k-5;
                xx = xx<0 ? -xx : (xx>IMW-1 ? 2*(IMW-1)-xx : xx);
                acc += c_gauss[k]*bufA[r*160+xx];
            }
            bufB[idx]=acc;
        }
        __syncthreads();
        for(int idx=tid; idx<8*160; idx+=nt){
            int j=idx/160, x=idx%160;
            int yb=y0+j;
            float acc=0.f;
            #pragma unroll
            for(int k=0;k<11;k++){
                int yy=yb+k-5;
                yy = yy<0 ? -yy : (yy>IMH-1 ? 2*(IMH-1)-yy : yy);
                acc += c_gauss[k]*bufB[(yy-(y0-5))*160+x];
            }
            bufA[idx]=acc;
        }
        __syncthreads();
        float* o=&out[(p*4+3)*HW];
        for(int idx=tid; idx<8*160; idx+=nt){
            int j=idx/160, x=idx%160;
            float acc=0.f;
            #pragma unroll
            for(int k=0;k<11;k++){
                int xx=x+k-5;
                xx = xx<0 ? -xx : (xx>IMW-1 ? 2*(IMW-1)-xx : xx);
                acc += c_gauss[k]*bufA[j*160+xx];
            }
            o[(y0+j)*IMW+x]=acc;
        }
    }
}

__global__ void __launch_bounds__(128) k_post(float* __restrict__ out){
    __shared__ __align__(16) float bufA[30*160];
    __shared__ __align__(16) float bufB[28*160];
    post_task8(bufA, bufB, blockIdx.x, out, threadIdx.x, 128);
}

// ---------------- launch ----------------
extern "C" void kernel_launch(void* const* d_in, const int* in_sizes, int n_in,
                              void* d_out, int out_size) {
    const float* trans=(const float*)d_in[0];
    const float* quat =(const float*)d_in[1];
    const float* uv   =(const float*)d_in[2];
    const float* ffeat=(const float*)d_in[3];
    const int*   faces=(const int*)  d_in[4];
    float* out=(float*)d_out;

    k_geom<<<NPASS, 640>>>(uv, faces, quat, trans);
    k_raster<<<dim3(NCHUNK,40,NPASS), 128>>>();
    k_merge<<<(NPASS*HW+255)/256, 256>>>(ffeat);
    k_post<<<1280, 128>>>(out);
}